// round 2
// baseline (speedup 1.0000x reference)
#include <cuda_runtime.h>
#include <math.h>

#define B_ 2
#define S_ 2048
#define H_ 4096
#define NH_ 32
#define HD_ 128
#define M_ (B_*S_)        /* 4096 rows of tokens */
#define N_QKV (3*H_)      /* 12288 */

// Scratch (allocation-free requirement -> device globals)
__device__ float g_qkv[(size_t)M_ * N_QKV];   // 201 MB
__device__ float g_attn[(size_t)M_ * H_];     // 67 MB
__device__ float g_inv_freq[64];

// ---------------------------------------------------------------------------
// inv_freq table (double precision -> matches f32 reference to ~1 ulp)
// ---------------------------------------------------------------------------
__global__ void init_invfreq_kernel() {
    int d = threadIdx.x;
    if (d < 64) {
        double e = exp(-((double)d / 64.0) * log(10000.0));
        g_inv_freq[d] = (float)e;
    }
}

// ---------------------------------------------------------------------------
// SGEMM: C[M,N] = A[M,K] * B[K,N], all row-major, M%128==0, N%128==0, K%8==0
// 128x128 block tile, BK=8, 256 threads, 8x8 register tile per thread.
// ---------------------------------------------------------------------------
__global__ __launch_bounds__(256) void sgemm_kernel(
    const float* __restrict__ A, const float* __restrict__ B,
    float* __restrict__ C, int Mdim, int Ndim, int Kdim)
{
    const int BM = 128, BN = 128, BK = 8, TM = 8, TN = 8;
    __shared__ float As[BK][132];   // padded: conflict-free transposed stores
    __shared__ float Bs[BK][BN];

    int tid = threadIdx.x;
    int tx = tid & 15;          // 0..15  (N direction)
    int ty = tid >> 4;          // 0..15  (M direction)
    int blockRow = blockIdx.y * BM;
    int blockCol = blockIdx.x * BN;

    int rowA = tid >> 1;            // 0..127
    int colA = (tid & 1) * 4;       // 0 or 4
    int rowB = tid >> 5;            // 0..7
    int colB = (tid & 31) * 4;      // 0..124

    float acc[TM][TN];
#pragma unroll
    for (int i = 0; i < TM; i++)
#pragma unroll
        for (int j = 0; j < TN; j++) acc[i][j] = 0.f;

    const float* Aptr = A + (size_t)blockRow * Kdim;
    const float* Bptr = B + blockCol;

    for (int k0 = 0; k0 < Kdim; k0 += BK) {
        float4 a4 = *(const float4*)(Aptr + (size_t)rowA * Kdim + k0 + colA);
        As[colA + 0][rowA] = a4.x;
        As[colA + 1][rowA] = a4.y;
        As[colA + 2][rowA] = a4.z;
        As[colA + 3][rowA] = a4.w;
        *(float4*)&Bs[rowB][colB] =
            *(const float4*)(Bptr + (size_t)(k0 + rowB) * Ndim + colB);
        __syncthreads();

#pragma unroll
        for (int kk = 0; kk < BK; kk++) {
            float regM[TM], regN[TN];
            float4 m0 = *(const float4*)&As[kk][ty * TM];
            float4 m1 = *(const float4*)&As[kk][ty * TM + 4];
            regM[0]=m0.x; regM[1]=m0.y; regM[2]=m0.z; regM[3]=m0.w;
            regM[4]=m1.x; regM[5]=m1.y; regM[6]=m1.z; regM[7]=m1.w;
            float4 n0 = *(const float4*)&Bs[kk][tx * TN];
            float4 n1 = *(const float4*)&Bs[kk][tx * TN + 4];
            regN[0]=n0.x; regN[1]=n0.y; regN[2]=n0.z; regN[3]=n0.w;
            regN[4]=n1.x; regN[5]=n1.y; regN[6]=n1.z; regN[7]=n1.w;
#pragma unroll
            for (int i = 0; i < TM; i++)
#pragma unroll
                for (int j = 0; j < TN; j++)
                    acc[i][j] += regM[i] * regN[j];
        }
        __syncthreads();
    }

#pragma unroll
    for (int i = 0; i < TM; i++) {
        int r = blockRow + ty * TM + i;
        float* crow = C + (size_t)r * Ndim + blockCol + tx * TN;
        *(float4*)(crow + 0) = make_float4(acc[i][0], acc[i][1], acc[i][2], acc[i][3]);
        *(float4*)(crow + 4) = make_float4(acc[i][4], acc[i][5], acc[i][6], acc[i][7]);
    }
}

// ---------------------------------------------------------------------------
// RoPE in-place on Q and K slices of g_qkv
// one thread per (token, head, d<64): rotates (d, d+64) for both q and k
// ---------------------------------------------------------------------------
__global__ void rope_kernel(const int* __restrict__ positions) {
    int idx = blockIdx.x * blockDim.x + threadIdx.x;
    if (idx >= M_ * NH_ * 64) return;
    int d = idx & 63;
    int h = (idx >> 6) & (NH_ - 1);
    int t = idx >> 11;                 // b*S + s
    float pos = (float)positions[t];
    float ang = pos * g_inv_freq[d];
    float s, c;
    sincosf(ang, &s, &c);
    size_t base = (size_t)t * N_QKV + h * HD_ + d;
    float q1 = g_qkv[base], q2 = g_qkv[base + 64];
    g_qkv[base]      = q1 * c - q2 * s;
    g_qkv[base + 64] = q2 * c + q1 * s;
    size_t kb = base + H_;
    float k1 = g_qkv[kb], k2 = g_qkv[kb + 64];
    g_qkv[kb]      = k1 * c - k2 * s;
    g_qkv[kb + 64] = k2 * c + k1 * s;
}

// ---------------------------------------------------------------------------
// Flash attention, fp32, causal. 64 q-rows per block, 64-wide k tiles.
// 256 threads. Online softmax. Dynamic smem ~113 KB.
// ---------------------------------------------------------------------------
#define QP 129
#define KP 129
#define VP 128
#define SP 65
#define FLASH_SMEM_BYTES ((64*QP + 64*KP + 64*VP + 64*SP) * 4)

__global__ __launch_bounds__(256) void flash_kernel() {
    extern __shared__ float sm[];
    float* Qs = sm;                  // [64][129]
    float* Ks = Qs + 64 * QP;        // [64][129]
    float* Vs = Ks + 64 * KP;        // [64][128]
    float* St = Vs + 64 * VP;        // [64][65]

    int tid = threadIdx.x;
    int qt = blockIdx.x, h = blockIdx.y, b = blockIdx.z;
    const float scale = 0.08838834764831845f;   // 128^-0.5

    // Load Q tile (rotated q from g_qkv)
    {
        size_t gbase = ((size_t)(b * S_ + qt * 64)) * N_QKV + h * HD_;
        for (int idx = tid; idx < 64 * 32; idx += 256) {
            int row = idx >> 5;
            int c = (idx & 31) << 2;
            float4 v = *(const float4*)(g_qkv + gbase + (size_t)row * N_QKV + c);
            float* dst = Qs + row * QP + c;
            dst[0] = v.x; dst[1] = v.y; dst[2] = v.z; dst[3] = v.w;
        }
    }

    int r  = tid >> 2;      // 0..63  owned q-row for softmax/output
    int qq = tid & 3;       // 0..3   column quarter (32 cols)
    int sy = tid >> 4;      // 0..15  score micro-tile row group
    int sx = tid & 15;      // 0..15  score micro-tile col group

    float m = -1e30f, l = 0.f;
    float4 O[8];
#pragma unroll
    for (int u = 0; u < 8; u++) O[u] = make_float4(0.f, 0.f, 0.f, 0.f);

    for (int kt = 0; kt <= qt; kt++) {
        __syncthreads();   // prior iter's Vs/St consumers done (also covers Q load)

        // Load K and V tiles
        size_t kbase = ((size_t)(b * S_ + kt * 64)) * N_QKV + H_ + h * HD_;
        size_t vbase = kbase + H_;
        for (int idx = tid; idx < 64 * 32; idx += 256) {
            int row = idx >> 5;
            int c = (idx & 31) << 2;
            float4 kv = *(const float4*)(g_qkv + kbase + (size_t)row * N_QKV + c);
            float* dk = Ks + row * KP + c;
            dk[0] = kv.x; dk[1] = kv.y; dk[2] = kv.z; dk[3] = kv.w;
            *(float4*)(Vs + row * VP + c) =
                *(const float4*)(g_qkv + vbase + (size_t)row * N_QKV + c);
        }
        __syncthreads();

        // Scores: 4x4 micro-tile per thread
        float acc[4][4];
#pragma unroll
        for (int i = 0; i < 4; i++)
#pragma unroll
            for (int j = 0; j < 4; j++) acc[i][j] = 0.f;

#pragma unroll 4
        for (int d = 0; d < 128; d++) {
            float qv[4], kv[4];
#pragma unroll
            for (int i = 0; i < 4; i++) qv[i] = Qs[(sy * 4 + i) * QP + d];
#pragma unroll
            for (int j = 0; j < 4; j++) kv[j] = Ks[(sx * 4 + j) * KP + d];
#pragma unroll
            for (int i = 0; i < 4; i++)
#pragma unroll
                for (int j = 0; j < 4; j++) acc[i][j] += qv[i] * kv[j];
        }

        int ig0 = qt * 64 + sy * 4, jg0 = kt * 64 + sx * 4;
#pragma unroll
        for (int i = 0; i < 4; i++)
#pragma unroll
            for (int j = 0; j < 4; j++) {
                float v = acc[i][j] * scale;
                if (jg0 + j > ig0 + i) v = -1e30f;
                St[(sy * 4 + i) * SP + sx * 4 + j] = v;
            }
        __syncthreads();

        // Online softmax on row r (4 threads per row)
        float tmax = -1e30f;
        int j0 = qq * 16;
#pragma unroll
        for (int j = 0; j < 16; j++) tmax = fmaxf(tmax, St[r * SP + j0 + j]);
        tmax = fmaxf(tmax, __shfl_xor_sync(0xFFFFFFFFu, tmax, 1));
        tmax = fmaxf(tmax, __shfl_xor_sync(0xFFFFFFFFu, tmax, 2));
        float nm = fmaxf(m, tmax);
        float corr = expf(m - nm);
        float psum = 0.f;
#pragma unroll
        for (int j = 0; j < 16; j++) {
            float p = expf(St[r * SP + j0 + j] - nm);
            St[r * SP + j0 + j] = p;
            psum += p;
        }
        psum += __shfl_xor_sync(0xFFFFFFFFu, psum, 1);
        psum += __shfl_xor_sync(0xFFFFFFFFu, psum, 2);
        l = l * corr + psum;
        m = nm;
#pragma unroll
        for (int u = 0; u < 8; u++) {
            O[u].x *= corr; O[u].y *= corr; O[u].z *= corr; O[u].w *= corr;
        }
        __syncwarp();   // P row r fully written by this warp's 4-thread group

        // O += P @ V  (thread owns row r, cols qq*32..qq*32+31)
#pragma unroll 2
        for (int j = 0; j < 64; j++) {
            float p = St[r * SP + j];
            const float4* vr = (const float4*)(Vs + j * VP + qq * 32);
#pragma unroll
            for (int u = 0; u < 8; u++) {
                float4 vv = vr[u];
                O[u].x += p * vv.x; O[u].y += p * vv.y;
                O[u].z += p * vv.z; O[u].w += p * vv.w;
            }
        }
    }

    float inv_l = 1.0f / l;
    size_t obase = ((size_t)(b * S_ + qt * 64 + r)) * H_ + h * HD_ + qq * 32;
#pragma unroll
    for (int u = 0; u < 8; u++) {
        float4 vv = O[u];
        vv.x *= inv_l; vv.y *= inv_l; vv.z *= inv_l; vv.w *= inv_l;
        *(float4*)(g_attn + obase + u * 4) = vv;
    }
}

// ---------------------------------------------------------------------------
// Launch
// ---------------------------------------------------------------------------
extern "C" void kernel_launch(void* const* d_in, const int* in_sizes, int n_in,
                              void* d_out, int out_size) {
    (void)in_sizes; (void)n_in; (void)out_size;
    const int*   positions = (const int*)d_in[0];
    const float* hidden    = (const float*)d_in[1];
    const float* w_qkv     = (const float*)d_in[2];
    const float* w_out     = (const float*)d_in[3];
    float* out = (float*)d_out;

    float *qkv_ptr, *attn_ptr;
    cudaGetSymbolAddress((void**)&qkv_ptr, g_qkv);
    cudaGetSymbolAddress((void**)&attn_ptr, g_attn);

    cudaFuncSetAttribute(flash_kernel,
                         cudaFuncAttributeMaxDynamicSharedMemorySize,
                         FLASH_SMEM_BYTES);

    // 0. inv_freq table (tiny; fill the pipe before the big GEMM)
    init_invfreq_kernel<<<1, 64>>>();

    // 1. QKV projection: [4096,4096] x [4096,12288]
    sgemm_kernel<<<dim3(N_QKV / 128, M_ / 128), 256>>>(
        hidden, w_qkv, qkv_ptr, M_, N_QKV, H_);

    // 2. RoPE (rotate q,k in place)
    rope_kernel<<<(M_ * NH_ * 64) / 256, 256>>>(positions);

    // 3. Causal flash attention
    flash_kernel<<<dim3(S_ / 64, NH_, B_), 256, FLASH_SMEM_BYTES>>>();

    // 4. Output projection: [4096,4096] x [4096,4096]
    sgemm_kernel<<<dim3(H_ / 128, M_ / 128), 256>>>(
        attn_ptr, w_out, out, M_, H_, H_);
}

// round 5
// speedup vs baseline: 1.5635x; 1.5635x over previous
#include <cuda_runtime.h>
#include <cuda_bf16.h>
#include <math.h>
#include <stdint.h>

#define B_ 2
#define S_ 2048
#define H_ 4096
#define NH_ 32
#define HD_ 128
#define M_ (B_*S_)        /* 4096 token rows */
#define N_QKV (3*H_)      /* 12288 */

// ---------------------------------------------------------------------------
// Scratch (allocation-free requirement -> device globals)
// ---------------------------------------------------------------------------
__device__ float g_qkv [(size_t)M_ * N_QKV];
__device__ float g_attn[(size_t)M_ * H_];
__device__ float g_inv_freq[64];

__device__ __nv_bfloat16 g_hid_hi [(size_t)M_ * H_];
__device__ __nv_bfloat16 g_hid_lo [(size_t)M_ * H_];
__device__ __nv_bfloat16 g_wqkvT_hi[(size_t)N_QKV * H_];   // [N,K]
__device__ __nv_bfloat16 g_wqkvT_lo[(size_t)N_QKV * H_];
__device__ __nv_bfloat16 g_woutT_hi[(size_t)H_ * H_];
__device__ __nv_bfloat16 g_woutT_lo[(size_t)H_ * H_];
__device__ __nv_bfloat16 g_attn_hi[(size_t)M_ * H_];
__device__ __nv_bfloat16 g_attn_lo[(size_t)M_ * H_];

// ---------------------------------------------------------------------------
// PTX helpers (sm_80-era only: ldmatrix / mma.sync / cp.async — valid on
// base compute_100 target; tcgen05 is NOT available in this toolchain)
// ---------------------------------------------------------------------------
__device__ __forceinline__ uint32_t smem_u32(const void* p) {
    uint32_t a;
    asm("{ .reg .u64 t; cvta.to.shared.u64 t, %1; cvt.u32.u64 %0, t; }"
        : "=r"(a) : "l"(p));
    return a;
}
__device__ __forceinline__ void ldm_x4(uint32_t* r, uint32_t addr) {
    asm volatile("ldmatrix.sync.aligned.m8n8.x4.shared.b16 {%0,%1,%2,%3}, [%4];"
        : "=r"(r[0]), "=r"(r[1]), "=r"(r[2]), "=r"(r[3]) : "r"(addr));
}
__device__ __forceinline__ void mma_bf16(float* d, const uint32_t* a,
                                         uint32_t b0, uint32_t b1) {
    asm volatile("mma.sync.aligned.m16n8k16.row.col.f32.bf16.bf16.f32 "
        "{%0,%1,%2,%3}, {%4,%5,%6,%7}, {%8,%9}, {%0,%1,%2,%3};"
        : "+f"(d[0]), "+f"(d[1]), "+f"(d[2]), "+f"(d[3])
        : "r"(a[0]), "r"(a[1]), "r"(a[2]), "r"(a[3]), "r"(b0), "r"(b1));
}
__device__ __forceinline__ void cp16(uint32_t saddr, const void* g) {
    asm volatile("cp.async.cg.shared.global [%0], [%1], 16;"
                 :: "r"(saddr), "l"(g));
}
#define CP_COMMIT() asm volatile("cp.async.commit_group;" ::: "memory")
#define CP_WAIT1()  asm volatile("cp.async.wait_group 1;" ::: "memory")

// ---------------------------------------------------------------------------
// inv_freq table
// ---------------------------------------------------------------------------
__global__ void init_invfreq_kernel() {
    int d = threadIdx.x;
    if (d < 64) {
        double e = exp(-((double)d / 64.0) * log(10000.0));
        g_inv_freq[d] = (float)e;
    }
}

// ---------------------------------------------------------------------------
// f32 -> bf16(hi) + bf16(lo) split, row-major
// ---------------------------------------------------------------------------
__global__ void split_kernel(const float* __restrict__ x,
                             __nv_bfloat16* __restrict__ hi,
                             __nv_bfloat16* __restrict__ lo, int n4)
{
    int i = blockIdx.x * 256 + threadIdx.x;
    if (i >= n4) return;
    float4 v = ((const float4*)x)[i];
    float vs[4] = {v.x, v.y, v.z, v.w};
    uint32_t hb[4], lb[4];
#pragma unroll
    for (int j = 0; j < 4; j++) {
        __nv_bfloat16 h = __float2bfloat16(vs[j]);
        __nv_bfloat16 l = __float2bfloat16(vs[j] - __bfloat162float(h));
        hb[j] = __bfloat16_as_ushort(h);
        lb[j] = __bfloat16_as_ushort(l);
    }
    ((uint2*)hi)[i] = make_uint2(hb[0] | (hb[1] << 16), hb[2] | (hb[3] << 16));
    ((uint2*)lo)[i] = make_uint2(lb[0] | (lb[1] << 16), lb[2] | (lb[3] << 16));
}

// ---------------------------------------------------------------------------
// f32 W[R,C] -> transposed bf16 hi/lo WT[C,R]
// ---------------------------------------------------------------------------
__global__ void tsplit_kernel(const float* __restrict__ W,
                              __nv_bfloat16* __restrict__ hiT,
                              __nv_bfloat16* __restrict__ loT, int R, int Cc)
{
    __shared__ float t[32][33];
    int tx = threadIdx.x, ty = threadIdx.y;        // (32, 8)
    int c0 = blockIdx.x * 32, r0 = blockIdx.y * 32;
#pragma unroll
    for (int j = 0; j < 4; j++)
        t[ty + 8*j][tx] = W[(size_t)(r0 + ty + 8*j) * Cc + c0 + tx];
    __syncthreads();
#pragma unroll
    for (int j = 0; j < 4; j++) {
        float v = t[tx][ty + 8*j];
        __nv_bfloat16 h = __float2bfloat16(v);
        __nv_bfloat16 l = __float2bfloat16(v - __bfloat162float(h));
        size_t o = (size_t)(c0 + ty + 8*j) * R + r0 + tx;
        hiT[o] = h;
        loT[o] = l;
    }
}

// ---------------------------------------------------------------------------
// Tensor-core (HMMA mma.sync) split-bf16 GEMM
//   C[M,N] f32 = A[M,K] x B  (B given transposed: BT[N,K])
// 128x128 CTA tile, BK=32, 256 thr (2x4 warps, 64x32 warp tile),
// cp.async double buffer. 3 terms: Ah*Bh + Ah*Bl + Al*Bh.
// ---------------------------------------------------------------------------
#define KPAD 40                               /* bf16 elems per smem row */
#define MAT_ELEMS (128 * KPAD)                /* 5120  */
#define STAGE_ELEMS (4 * MAT_ELEMS)           /* 20480 */
#define STAGE_BYTES (STAGE_ELEMS * 2)         /* 40960 */
#define GEMM_SMEM (2 * STAGE_BYTES)           /* 81920 */

__global__ __launch_bounds__(256) void mma_gemm_kernel(
    const __nv_bfloat16* __restrict__ Ah, const __nv_bfloat16* __restrict__ Al,
    const __nv_bfloat16* __restrict__ Bh, const __nv_bfloat16* __restrict__ Bl,
    float* __restrict__ C, int Ndim, int Kdim)
{
    extern __shared__ __nv_bfloat16 sm_[];
    const uint32_t sbase = smem_u32(sm_);
    const int tid = threadIdx.x;
    const int lane = tid & 31, wid = tid >> 5;
    const int wm = wid >> 2, wn = wid & 3;       // 2 x 4 warp grid
    const int bm = blockIdx.x * 128, bn = blockIdx.y * 128;
    const int nch = Kdim >> 5;                   // K chunks of 32

    // ---- stage loader: 2048 x 16B cp.async (8 per thread) ----
    // idx -> mat(0..3: Ah,Al,Bh,Bl), row(0..127), chunk(0..3)
    auto load_stage = [&](int ch, int s) {
        int k0 = ch << 5;
#pragma unroll
        for (int t = 0; t < 8; t++) {
            int idx = tid + t * 256;
            int mat = idx >> 9;
            int r   = (idx >> 2) & 127;
            int c   = (idx & 3) << 3;            // bf16 offset (0,8,16,24)
            const __nv_bfloat16* gp;
            if (mat == 0)      gp = Ah + (size_t)(bm + r) * Kdim + k0 + c;
            else if (mat == 1) gp = Al + (size_t)(bm + r) * Kdim + k0 + c;
            else if (mat == 2) gp = Bh + (size_t)(bn + r) * Kdim + k0 + c;
            else               gp = Bl + (size_t)(bn + r) * Kdim + k0 + c;
            uint32_t so = sbase + (uint32_t)(s * STAGE_ELEMS + mat * MAT_ELEMS
                                             + r * KPAD + c) * 2;
            cp16(so, gp);
        }
    };

    float acc[4][4][4];
#pragma unroll
    for (int mt = 0; mt < 4; mt++)
#pragma unroll
        for (int nt = 0; nt < 4; nt++)
#pragma unroll
            for (int e = 0; e < 4; e++) acc[mt][nt][e] = 0.f;

    load_stage(0, 0);
    CP_COMMIT();

    const int lrow = lane & 15;                  // ldmatrix row select
    const int lkof = (lane >> 4) << 3;           // ldmatrix k-half select

    for (int ch = 0; ch < nch; ch++) {
        int s = ch & 1;
        if (ch + 1 < nch) load_stage(ch + 1, s ^ 1);
        CP_COMMIT();
        CP_WAIT1();
        __syncthreads();

        uint32_t stA_h = sbase + (uint32_t)(s * STAGE_ELEMS) * 2;
        uint32_t stA_l = stA_h + MAT_ELEMS * 2;
        uint32_t stB_h = stA_h + 2 * MAT_ELEMS * 2;
        uint32_t stB_l = stA_h + 3 * MAT_ELEMS * 2;

#pragma unroll
        for (int kk = 0; kk < 2; kk++) {
            int ko = (kk << 4) + lkof;           // k offset within BK=32
            uint32_t ah[4][4], al[4][4], bh[2][4], bl[2][4];
#pragma unroll
            for (int mt = 0; mt < 4; mt++) {
                uint32_t ro = (uint32_t)((wm * 64 + mt * 16 + lrow) * KPAD + ko) * 2;
                ldm_x4(ah[mt], stA_h + ro);
                ldm_x4(al[mt], stA_l + ro);
            }
#pragma unroll
            for (int L = 0; L < 2; L++) {
                uint32_t ro = (uint32_t)((wn * 32 + L * 16 + lrow) * KPAD + ko) * 2;
                ldm_x4(bh[L], stB_h + ro);
                ldm_x4(bl[L], stB_l + ro);
            }
#pragma unroll
            for (int mt = 0; mt < 4; mt++)
#pragma unroll
                for (int nt = 0; nt < 4; nt++) {
                    int L = nt >> 1, p = nt & 1;
                    mma_bf16(acc[mt][nt], ah[mt], bh[L][p], bh[L][p + 2]);
                    mma_bf16(acc[mt][nt], ah[mt], bl[L][p], bl[L][p + 2]);
                    mma_bf16(acc[mt][nt], al[mt], bh[L][p], bh[L][p + 2]);
                }
        }
        __syncthreads();
    }

    // ---- epilogue: d0,d1 -> (row, col..col+1); d2,d3 -> (row+8, ...) ----
#pragma unroll
    for (int mt = 0; mt < 4; mt++) {
        int row = bm + wm * 64 + mt * 16 + (lane >> 2);
#pragma unroll
        for (int nt = 0; nt < 4; nt++) {
            int col = bn + wn * 32 + nt * 8 + (lane & 3) * 2;
            *(float2*)(C + (size_t)row * Ndim + col) =
                make_float2(acc[mt][nt][0], acc[mt][nt][1]);
            *(float2*)(C + (size_t)(row + 8) * Ndim + col) =
                make_float2(acc[mt][nt][2], acc[mt][nt][3]);
        }
    }
}

// ---------------------------------------------------------------------------
// RoPE in-place on Q and K slices of g_qkv
// ---------------------------------------------------------------------------
__global__ void rope_kernel(const int* __restrict__ positions) {
    int idx = blockIdx.x * blockDim.x + threadIdx.x;
    if (idx >= M_ * NH_ * 64) return;
    int d = idx & 63;
    int h = (idx >> 6) & (NH_ - 1);
    int t = idx >> 11;
    float pos = (float)positions[t];
    float ang = pos * g_inv_freq[d];
    float s, c;
    sincosf(ang, &s, &c);
    size_t base = (size_t)t * N_QKV + h * HD_ + d;
    float q1 = g_qkv[base], q2 = g_qkv[base + 64];
    g_qkv[base]      = q1 * c - q2 * s;
    g_qkv[base + 64] = q2 * c + q1 * s;
    size_t kb = base + H_;
    float k1 = g_qkv[kb], k2 = g_qkv[kb + 64];
    g_qkv[kb]      = k1 * c - k2 * s;
    g_qkv[kb + 64] = k2 * c + k1 * s;
}

// ---------------------------------------------------------------------------
// Flash attention, fp32, causal (unchanged R2-passing version)
// ---------------------------------------------------------------------------
#define QP 129
#define KP 129
#define VP 128
#define SP 65
#define FLASH_SMEM_BYTES ((64*QP + 64*KP + 64*VP + 64*SP) * 4)

__global__ __launch_bounds__(256) void flash_kernel() {
    extern __shared__ float sm[];
    float* Qs = sm;
    float* Ks = Qs + 64 * QP;
    float* Vs = Ks + 64 * KP;
    float* St = Vs + 64 * VP;

    int tid = threadIdx.x;
    int qt = blockIdx.x, h = blockIdx.y, b = blockIdx.z;
    const float scale = 0.08838834764831845f;

    {
        size_t gbase = ((size_t)(b * S_ + qt * 64)) * N_QKV + h * HD_;
        for (int idx = tid; idx < 64 * 32; idx += 256) {
            int row = idx >> 5;
            int c = (idx & 31) << 2;
            float4 v = *(const float4*)(g_qkv + gbase + (size_t)row * N_QKV + c);
            float* dst = Qs + row * QP + c;
            dst[0] = v.x; dst[1] = v.y; dst[2] = v.z; dst[3] = v.w;
        }
    }

    int r  = tid >> 2;
    int qq = tid & 3;
    int sy = tid >> 4;
    int sx = tid & 15;

    float m = -1e30f, l = 0.f;
    float4 O[8];
#pragma unroll
    for (int u = 0; u < 8; u++) O[u] = make_float4(0.f, 0.f, 0.f, 0.f);

    for (int kt = 0; kt <= qt; kt++) {
        __syncthreads();

        size_t kbase = ((size_t)(b * S_ + kt * 64)) * N_QKV + H_ + h * HD_;
        size_t vbase = kbase + H_;
        for (int idx = tid; idx < 64 * 32; idx += 256) {
            int row = idx >> 5;
            int c = (idx & 31) << 2;
            float4 kv = *(const float4*)(g_qkv + kbase + (size_t)row * N_QKV + c);
            float* dk = Ks + row * KP + c;
            dk[0] = kv.x; dk[1] = kv.y; dk[2] = kv.z; dk[3] = kv.w;
            *(float4*)(Vs + row * VP + c) =
                *(const float4*)(g_qkv + vbase + (size_t)row * N_QKV + c);
        }
        __syncthreads();

        float acc[4][4];
#pragma unroll
        for (int i = 0; i < 4; i++)
#pragma unroll
            for (int j = 0; j < 4; j++) acc[i][j] = 0.f;

#pragma unroll 4
        for (int d = 0; d < 128; d++) {
            float qv[4], kv[4];
#pragma unroll
            for (int i = 0; i < 4; i++) qv[i] = Qs[(sy * 4 + i) * QP + d];
#pragma unroll
            for (int j = 0; j < 4; j++) kv[j] = Ks[(sx * 4 + j) * KP + d];
#pragma unroll
            for (int i = 0; i < 4; i++)
#pragma unroll
                for (int j = 0; j < 4; j++) acc[i][j] += qv[i] * kv[j];
        }

        int ig0 = qt * 64 + sy * 4, jg0 = kt * 64 + sx * 4;
#pragma unroll
        for (int i = 0; i < 4; i++)
#pragma unroll
            for (int j = 0; j < 4; j++) {
                float v = acc[i][j] * scale;
                if (jg0 + j > ig0 + i) v = -1e30f;
                St[(sy * 4 + i) * SP + sx * 4 + j] = v;
            }
        __syncthreads();

        float tmax = -1e30f;
        int j0 = qq * 16;
#pragma unroll
        for (int j = 0; j < 16; j++) tmax = fmaxf(tmax, St[r * SP + j0 + j]);
        tmax = fmaxf(tmax, __shfl_xor_sync(0xFFFFFFFFu, tmax, 1));
        tmax = fmaxf(tmax, __shfl_xor_sync(0xFFFFFFFFu, tmax, 2));
        float nm = fmaxf(m, tmax);
        float corr = expf(m - nm);
        float psum = 0.f;
#pragma unroll
        for (int j = 0; j < 16; j++) {
            float p = expf(St[r * SP + j0 + j] - nm);
            St[r * SP + j0 + j] = p;
            psum += p;
        }
        psum += __shfl_xor_sync(0xFFFFFFFFu, psum, 1);
        psum += __shfl_xor_sync(0xFFFFFFFFu, psum, 2);
        l = l * corr + psum;
        m = nm;
#pragma unroll
        for (int u = 0; u < 8; u++) {
            O[u].x *= corr; O[u].y *= corr; O[u].z *= corr; O[u].w *= corr;
        }
        __syncwarp();

#pragma unroll 2
        for (int j = 0; j < 64; j++) {
            float p = St[r * SP + j];
            const float4* vr = (const float4*)(Vs + j * VP + qq * 32);
#pragma unroll
            for (int u = 0; u < 8; u++) {
                float4 vv = vr[u];
                O[u].x += p * vv.x; O[u].y += p * vv.y;
                O[u].z += p * vv.z; O[u].w += p * vv.w;
            }
        }
    }

    float inv_l = 1.0f / l;
    size_t obase = ((size_t)(b * S_ + qt * 64 + r)) * H_ + h * HD_ + qq * 32;
#pragma unroll
    for (int u = 0; u < 8; u++) {
        float4 vv = O[u];
        vv.x *= inv_l; vv.y *= inv_l; vv.z *= inv_l; vv.w *= inv_l;
        *(float4*)(g_attn + obase + u * 4) = vv;
    }
}

// ---------------------------------------------------------------------------
// Launch
// ---------------------------------------------------------------------------
extern "C" void kernel_launch(void* const* d_in, const int* in_sizes, int n_in,
                              void* d_out, int out_size) {
    (void)in_sizes; (void)n_in; (void)out_size;
    const int*   positions = (const int*)d_in[0];
    const float* hidden    = (const float*)d_in[1];
    const float* w_qkv     = (const float*)d_in[2];
    const float* w_out     = (const float*)d_in[3];
    float* out = (float*)d_out;

    float *qkv_p, *attn_p;
    __nv_bfloat16 *hid_h, *hid_l, *wqkv_h, *wqkv_l, *wout_h, *wout_l, *at_h, *at_l;
    cudaGetSymbolAddress((void**)&qkv_p,  g_qkv);
    cudaGetSymbolAddress((void**)&attn_p, g_attn);
    cudaGetSymbolAddress((void**)&hid_h,  g_hid_hi);
    cudaGetSymbolAddress((void**)&hid_l,  g_hid_lo);
    cudaGetSymbolAddress((void**)&wqkv_h, g_wqkvT_hi);
    cudaGetSymbolAddress((void**)&wqkv_l, g_wqkvT_lo);
    cudaGetSymbolAddress((void**)&wout_h, g_woutT_hi);
    cudaGetSymbolAddress((void**)&wout_l, g_woutT_lo);
    cudaGetSymbolAddress((void**)&at_h,   g_attn_hi);
    cudaGetSymbolAddress((void**)&at_l,   g_attn_lo);

    cudaFuncSetAttribute(flash_kernel,
                         cudaFuncAttributeMaxDynamicSharedMemorySize,
                         FLASH_SMEM_BYTES);
    cudaFuncSetAttribute(mma_gemm_kernel,
                         cudaFuncAttributeMaxDynamicSharedMemorySize,
                         GEMM_SMEM);

    // 0. inv_freq table
    init_invfreq_kernel<<<1, 64>>>();

    // 1. bf16 hi/lo conversions
    split_kernel<<<(M_ * H_ / 4 + 255) / 256, 256>>>(hidden, hid_h, hid_l, M_ * H_ / 4);
    tsplit_kernel<<<dim3(N_QKV / 32, H_ / 32), dim3(32, 8)>>>(w_qkv, wqkv_h, wqkv_l, H_, N_QKV);
    tsplit_kernel<<<dim3(H_ / 32, H_ / 32), dim3(32, 8)>>>(w_out, wout_h, wout_l, H_, H_);

    // 2. QKV projection on tensor cores (HMMA): [4096,4096] x [4096,12288]
    mma_gemm_kernel<<<dim3(M_ / 128, N_QKV / 128), 256, GEMM_SMEM>>>(
        hid_h, hid_l, wqkv_h, wqkv_l, qkv_p, N_QKV, H_);

    // 3. RoPE
    rope_kernel<<<(M_ * NH_ * 64) / 256, 256>>>(positions);

    // 4. Causal flash attention (fp32)
    flash_kernel<<<dim3(S_ / 64, NH_, B_), 256, FLASH_SMEM_BYTES>>>();

    // 5. Split attention output, then output projection on tensor cores
    split_kernel<<<(M_ * H_ / 4 + 255) / 256, 256>>>(attn_p, at_h, at_l, M_ * H_ / 4);
    mma_gemm_kernel<<<dim3(M_ / 128, H_ / 128), 256, GEMM_SMEM>>>(
        at_h, at_l, wout_h, wout_l, out, H_, H_);
}

// round 7
// speedup vs baseline: 3.5837x; 2.2921x over previous
#include <cuda_runtime.h>
#include <cuda_bf16.h>
#include <math.h>
#include <stdint.h>

#define B_ 2
#define S_ 2048
#define H_ 4096
#define NH_ 32
#define HD_ 128
#define M_ (B_*S_)        /* 4096 token rows */
#define N_QKV (3*H_)      /* 12288 */

// ---------------------------------------------------------------------------
// Scratch (allocation-free requirement -> device globals)
// ---------------------------------------------------------------------------
__device__ float g_qkv [(size_t)M_ * N_QKV];
__device__ float g_attn[(size_t)M_ * H_];
__device__ float g_inv_freq[64];

__device__ __nv_bfloat16 g_hid_hi [(size_t)M_ * H_];
__device__ __nv_bfloat16 g_hid_lo [(size_t)M_ * H_];
__device__ __nv_bfloat16 g_wqkvT_hi[(size_t)N_QKV * H_];   // [N,K]
__device__ __nv_bfloat16 g_wqkvT_lo[(size_t)N_QKV * H_];
__device__ __nv_bfloat16 g_woutT_hi[(size_t)H_ * H_];
__device__ __nv_bfloat16 g_woutT_lo[(size_t)H_ * H_];
__device__ __nv_bfloat16 g_attn_hi[(size_t)M_ * H_];
__device__ __nv_bfloat16 g_attn_lo[(size_t)M_ * H_];

// ---------------------------------------------------------------------------
// PTX helpers (sm_80-era: ldmatrix / mma.sync / cp.async — valid on base
// compute_100 target; tcgen05 is NOT available in this toolchain)
// ---------------------------------------------------------------------------
__device__ __forceinline__ uint32_t smem_u32(const void* p) {
    uint32_t a;
    asm("{ .reg .u64 t; cvta.to.shared.u64 t, %1; cvt.u32.u64 %0, t; }"
        : "=r"(a) : "l"(p));
    return a;
}
__device__ __forceinline__ void ldm_x4(uint32_t* r, uint32_t addr) {
    asm volatile("ldmatrix.sync.aligned.m8n8.x4.shared.b16 {%0,%1,%2,%3}, [%4];"
        : "=r"(r[0]), "=r"(r[1]), "=r"(r[2]), "=r"(r[3]) : "r"(addr));
}
__device__ __forceinline__ void ldm_x4_t(uint32_t* r, uint32_t addr) {
    asm volatile("ldmatrix.sync.aligned.m8n8.x4.trans.shared.b16 {%0,%1,%2,%3}, [%4];"
        : "=r"(r[0]), "=r"(r[1]), "=r"(r[2]), "=r"(r[3]) : "r"(addr));
}
__device__ __forceinline__ void mma_bf16(float* d, const uint32_t* a,
                                         uint32_t b0, uint32_t b1) {
    asm volatile("mma.sync.aligned.m16n8k16.row.col.f32.bf16.bf16.f32 "
        "{%0,%1,%2,%3}, {%4,%5,%6,%7}, {%8,%9}, {%0,%1,%2,%3};"
        : "+f"(d[0]), "+f"(d[1]), "+f"(d[2]), "+f"(d[3])
        : "r"(a[0]), "r"(a[1]), "r"(a[2]), "r"(a[3]), "r"(b0), "r"(b1));
}
__device__ __forceinline__ void cp16(uint32_t saddr, const void* g) {
    asm volatile("cp.async.cg.shared.global [%0], [%1], 16;"
                 :: "r"(saddr), "l"(g));
}
#define CP_COMMIT() asm volatile("cp.async.commit_group;" ::: "memory")
#define CP_WAIT1()  asm volatile("cp.async.wait_group 1;" ::: "memory")

// split a float4 into packed bf16 hi/lo uint2
__device__ __forceinline__ void split4(float4 v, uint2& ph, uint2& pl) {
    float vs[4] = {v.x, v.y, v.z, v.w};
    uint32_t hb[4], lb[4];
#pragma unroll
    for (int j = 0; j < 4; j++) {
        __nv_bfloat16 h = __float2bfloat16(vs[j]);
        __nv_bfloat16 l = __float2bfloat16(vs[j] - __bfloat162float(h));
        hb[j] = __bfloat16_as_ushort(h);
        lb[j] = __bfloat16_as_ushort(l);
    }
    ph = make_uint2(hb[0] | (hb[1] << 16), hb[2] | (hb[3] << 16));
    pl = make_uint2(lb[0] | (lb[1] << 16), lb[2] | (lb[3] << 16));
}

// ---------------------------------------------------------------------------
// inv_freq table
// ---------------------------------------------------------------------------
__global__ void init_invfreq_kernel() {
    int d = threadIdx.x;
    if (d < 64) {
        double e = exp(-((double)d / 64.0) * log(10000.0));
        g_inv_freq[d] = (float)e;
    }
}

// ---------------------------------------------------------------------------
// f32 -> bf16(hi/lo) split, row-major
// ---------------------------------------------------------------------------
__global__ void split_kernel(const float* __restrict__ x,
                             __nv_bfloat16* __restrict__ hi,
                             __nv_bfloat16* __restrict__ lo, int n4)
{
    int i = blockIdx.x * 256 + threadIdx.x;
    if (i >= n4) return;
    uint2 ph, pl;
    split4(((const float4*)x)[i], ph, pl);
    ((uint2*)hi)[i] = ph;
    ((uint2*)lo)[i] = pl;
}

// ---------------------------------------------------------------------------
// f32 W[R,C] -> transposed bf16 hi/lo WT[C,R]
// ---------------------------------------------------------------------------
__global__ void tsplit_kernel(const float* __restrict__ W,
                              __nv_bfloat16* __restrict__ hiT,
                              __nv_bfloat16* __restrict__ loT, int R, int Cc)
{
    __shared__ float t[32][33];
    int tx = threadIdx.x, ty = threadIdx.y;        // (32, 8)
    int c0 = blockIdx.x * 32, r0 = blockIdx.y * 32;
#pragma unroll
    for (int j = 0; j < 4; j++)
        t[ty + 8*j][tx] = W[(size_t)(r0 + ty + 8*j) * Cc + c0 + tx];
    __syncthreads();
#pragma unroll
    for (int j = 0; j < 4; j++) {
        float v = t[tx][ty + 8*j];
        __nv_bfloat16 h = __float2bfloat16(v);
        __nv_bfloat16 l = __float2bfloat16(v - __bfloat162float(h));
        size_t o = (size_t)(c0 + ty + 8*j) * R + r0 + tx;
        hiT[o] = h;
        loT[o] = l;
    }
}

// ---------------------------------------------------------------------------
// HMMA split-bf16 GEMM (unchanged from R5-passing version)
// ---------------------------------------------------------------------------
#define KPAD 40
#define MAT_ELEMS (128 * KPAD)
#define STAGE_ELEMS (4 * MAT_ELEMS)
#define STAGE_BYTES (STAGE_ELEMS * 2)
#define GEMM_SMEM (2 * STAGE_BYTES)

__global__ __launch_bounds__(256) void mma_gemm_kernel(
    const __nv_bfloat16* __restrict__ Ah, const __nv_bfloat16* __restrict__ Al,
    const __nv_bfloat16* __restrict__ Bh, const __nv_bfloat16* __restrict__ Bl,
    float* __restrict__ C, int Ndim, int Kdim)
{
    extern __shared__ __nv_bfloat16 sm_[];
    const uint32_t sbase = smem_u32(sm_);
    const int tid = threadIdx.x;
    const int lane = tid & 31, wid = tid >> 5;
    const int wm = wid >> 2, wn = wid & 3;
    const int bm = blockIdx.x * 128, bn = blockIdx.y * 128;
    const int nch = Kdim >> 5;

    auto load_stage = [&](int ch, int s) {
        int k0 = ch << 5;
#pragma unroll
        for (int t = 0; t < 8; t++) {
            int idx = tid + t * 256;
            int mat = idx >> 9;
            int r   = (idx >> 2) & 127;
            int c   = (idx & 3) << 3;
            const __nv_bfloat16* gp;
            if (mat == 0)      gp = Ah + (size_t)(bm + r) * Kdim + k0 + c;
            else if (mat == 1) gp = Al + (size_t)(bm + r) * Kdim + k0 + c;
            else if (mat == 2) gp = Bh + (size_t)(bn + r) * Kdim + k0 + c;
            else               gp = Bl + (size_t)(bn + r) * Kdim + k0 + c;
            uint32_t so = sbase + (uint32_t)(s * STAGE_ELEMS + mat * MAT_ELEMS
                                             + r * KPAD + c) * 2;
            cp16(so, gp);
        }
    };

    float acc[4][4][4];
#pragma unroll
    for (int mt = 0; mt < 4; mt++)
#pragma unroll
        for (int nt = 0; nt < 4; nt++)
#pragma unroll
            for (int e = 0; e < 4; e++) acc[mt][nt][e] = 0.f;

    load_stage(0, 0);
    CP_COMMIT();

    const int lrow = lane & 15;
    const int lkof = (lane >> 4) << 3;

    for (int ch = 0; ch < nch; ch++) {
        int s = ch & 1;
        if (ch + 1 < nch) load_stage(ch + 1, s ^ 1);
        CP_COMMIT();
        CP_WAIT1();
        __syncthreads();

        uint32_t stA_h = sbase + (uint32_t)(s * STAGE_ELEMS) * 2;
        uint32_t stA_l = stA_h + MAT_ELEMS * 2;
        uint32_t stB_h = stA_h + 2 * MAT_ELEMS * 2;
        uint32_t stB_l = stA_h + 3 * MAT_ELEMS * 2;

#pragma unroll
        for (int kk = 0; kk < 2; kk++) {
            int ko = (kk << 4) + lkof;
            uint32_t ah[4][4], al[4][4], bh[2][4], bl[2][4];
#pragma unroll
            for (int mt = 0; mt < 4; mt++) {
                uint32_t ro = (uint32_t)((wm * 64 + mt * 16 + lrow) * KPAD + ko) * 2;
                ldm_x4(ah[mt], stA_h + ro);
                ldm_x4(al[mt], stA_l + ro);
            }
#pragma unroll
            for (int L = 0; L < 2; L++) {
                uint32_t ro = (uint32_t)((wn * 32 + L * 16 + lrow) * KPAD + ko) * 2;
                ldm_x4(bh[L], stB_h + ro);
                ldm_x4(bl[L], stB_l + ro);
            }
#pragma unroll
            for (int mt = 0; mt < 4; mt++)
#pragma unroll
                for (int nt = 0; nt < 4; nt++) {
                    int L = nt >> 1, p = nt & 1;
                    mma_bf16(acc[mt][nt], ah[mt], bh[L][p], bh[L][p + 2]);
                    mma_bf16(acc[mt][nt], ah[mt], bl[L][p], bl[L][p + 2]);
                    mma_bf16(acc[mt][nt], al[mt], bh[L][p], bh[L][p + 2]);
                }
        }
        __syncthreads();
    }

#pragma unroll
    for (int mt = 0; mt < 4; mt++) {
        int row = bm + wm * 64 + mt * 16 + (lane >> 2);
#pragma unroll
        for (int nt = 0; nt < 4; nt++) {
            int col = bn + wn * 32 + nt * 8 + (lane & 3) * 2;
            *(float2*)(C + (size_t)row * Ndim + col) =
                make_float2(acc[mt][nt][0], acc[mt][nt][1]);
            *(float2*)(C + (size_t)(row + 8) * Ndim + col) =
                make_float2(acc[mt][nt][2], acc[mt][nt][3]);
        }
    }
}

// ---------------------------------------------------------------------------
// RoPE in-place on Q and K slices of g_qkv
// ---------------------------------------------------------------------------
__global__ void rope_kernel(const int* __restrict__ positions) {
    int idx = blockIdx.x * blockDim.x + threadIdx.x;
    if (idx >= M_ * NH_ * 64) return;
    int d = idx & 63;
    int h = (idx >> 6) & (NH_ - 1);
    int t = idx >> 11;
    float pos = (float)positions[t];
    float ang = pos * g_inv_freq[d];
    float s, c;
    sincosf(ang, &s, &c);
    size_t base = (size_t)t * N_QKV + h * HD_ + d;
    float q1 = g_qkv[base], q2 = g_qkv[base + 64];
    g_qkv[base]      = q1 * c - q2 * s;
    g_qkv[base + 64] = q2 * c + q1 * s;
    size_t kb = base + H_;
    float k1 = g_qkv[kb], k2 = g_qkv[kb + 64];
    g_qkv[kb]      = k1 * c - k2 * s;
    g_qkv[kb + 64] = k2 * c + k1 * s;
}

// ---------------------------------------------------------------------------
// Flash attention on tensor cores, bf16-split (3-term), causal.
// 64 q-rows/CTA, 64-key tiles, 8 warps (4 m-strips x 2), O in mma accums.
// ---------------------------------------------------------------------------
#define FQPAD 136          /* row stride (bf16) for Q/K/V smem tiles */
#define FPPAD 72           /* row stride for P tiles */
#define OFF_QH 0
#define OFF_QL 8704
#define OFF_KH 17408
#define OFF_KL 26112
#define OFF_VH 34816
#define OFF_VL 43520
#define OFF_PH 52224
#define OFF_PL 56832
#define FLT_OFF 122880     /* byte offset of f32 arrays (61440 bf16 elems) */
#define FLASH_SMEM (FLT_OFF + 1792)

__global__ __launch_bounds__(256, 1) void flash_mma_kernel() {
    extern __shared__ char fsm[];
    const uint32_t sb = smem_u32(fsm);
    __nv_bfloat16* bsm = (__nv_bfloat16*)fsm;
    float* m_s    = (float*)(fsm + FLT_OFF);           // [64]
    float* l_s    = m_s + 64;
    float* corr_s = m_s + 128;
    float* pmax   = m_s + 192;                         // [64][2]
    float* psum   = m_s + 320;                         // [64][2]

    const int tid = threadIdx.x;
    const int lane = tid & 31, wid = tid >> 5;
    const int wm = wid >> 1, wn = wid & 1;             // 4 x 2 warps
    const int qt = blockIdx.x, h = blockIdx.y, b = blockIdx.z;
    const float scale = 0.08838834764831845f;          // 128^-0.5
    const int lrow = lane & 15;
    const int lkof = (lane >> 4) << 3;
    const int qr   = lane >> 2;                        // fragment row 0..7
    const int qc2  = (lane & 3) * 2;                   // fragment col pair

    // ---- init state + load Q (scaled) ----
    if (tid < 64) { m_s[tid] = -1e30f; l_s[tid] = 0.f; }
    {
        size_t gbase = ((size_t)(b * S_ + qt * 64)) * N_QKV + h * HD_;
        for (int idx = tid; idx < 64 * 32; idx += 256) {
            int row = idx >> 5, c4 = (idx & 31) << 2;
            float4 v = *(const float4*)(g_qkv + gbase + (size_t)row * N_QKV + c4);
            v.x *= scale; v.y *= scale; v.z *= scale; v.w *= scale;
            uint2 ph, pl;
            split4(v, ph, pl);
            *(uint2*)(bsm + OFF_QH + row * FQPAD + c4) = ph;
            *(uint2*)(bsm + OFF_QL + row * FQPAD + c4) = pl;
        }
    }

    float oacc[8][4];
#pragma unroll
    for (int nt = 0; nt < 8; nt++)
#pragma unroll
        for (int e = 0; e < 4; e++) oacc[nt][e] = 0.f;

    for (int kt = 0; kt <= qt; kt++) {
        __syncthreads();   // prior iter's V/P consumers done (covers init too)

        // ---- load K,V tiles (f32 -> bf16 hi/lo smem) ----
        {
            size_t kbase = ((size_t)(b * S_ + kt * 64)) * N_QKV + H_ + h * HD_;
            size_t vbase = kbase + H_;
            for (int idx = tid; idx < 64 * 32; idx += 256) {
                int row = idx >> 5, c4 = (idx & 31) << 2;
                uint2 ph, pl;
                split4(*(const float4*)(g_qkv + kbase + (size_t)row * N_QKV + c4), ph, pl);
                *(uint2*)(bsm + OFF_KH + row * FQPAD + c4) = ph;
                *(uint2*)(bsm + OFF_KL + row * FQPAD + c4) = pl;
                split4(*(const float4*)(g_qkv + vbase + (size_t)row * N_QKV + c4), ph, pl);
                *(uint2*)(bsm + OFF_VH + row * FQPAD + c4) = ph;
                *(uint2*)(bsm + OFF_VL + row * FQPAD + c4) = pl;
            }
        }
        __syncthreads();

        // ---- S = Q K^T (3-term split), warp tile 16 x 32 ----
        float sacc[4][4];
#pragma unroll
        for (int nt = 0; nt < 4; nt++)
#pragma unroll
            for (int e = 0; e < 4; e++) sacc[nt][e] = 0.f;

#pragma unroll
        for (int kc = 0; kc < 8; kc++) {
            uint32_t ah[4], al[4], bh[2][4], bl[2][4];
            uint32_t qo = sb + (uint32_t)((wm * 16 + lrow) * FQPAD + kc * 16 + lkof) * 2;
            ldm_x4(ah, qo + OFF_QH * 2);
            ldm_x4(al, qo + OFF_QL * 2);
#pragma unroll
            for (int L = 0; L < 2; L++) {
                uint32_t ko = sb + (uint32_t)((wn * 32 + L * 16 + lrow) * FQPAD
                                              + kc * 16 + lkof) * 2;
                ldm_x4(bh[L], ko + OFF_KH * 2);
                ldm_x4(bl[L], ko + OFF_KL * 2);
            }
#pragma unroll
            for (int nt = 0; nt < 4; nt++) {
                int L = nt >> 1, p = nt & 1;
                mma_bf16(sacc[nt], ah, bh[L][p], bh[L][p + 2]);
                mma_bf16(sacc[nt], ah, bl[L][p], bl[L][p + 2]);
                mma_bf16(sacc[nt], al, bh[L][p], bh[L][p + 2]);
            }
        }

        // ---- causal mask (diagonal tile only) ----
        int r0 = wm * 16 + qr;
        if (kt == qt) {
#pragma unroll
            for (int nt = 0; nt < 4; nt++) {
                int c = wn * 32 + nt * 8 + qc2;
                if (c     > r0    ) sacc[nt][0] = -1e30f;
                if (c + 1 > r0    ) sacc[nt][1] = -1e30f;
                if (c     > r0 + 8) sacc[nt][2] = -1e30f;
                if (c + 1 > r0 + 8) sacc[nt][3] = -1e30f;
            }
        }

        // ---- row max (warp partial -> smem) ----
        float mx0 = -1e30f, mx1 = -1e30f;
#pragma unroll
        for (int nt = 0; nt < 4; nt++) {
            mx0 = fmaxf(mx0, fmaxf(sacc[nt][0], sacc[nt][1]));
            mx1 = fmaxf(mx1, fmaxf(sacc[nt][2], sacc[nt][3]));
        }
        mx0 = fmaxf(mx0, __shfl_xor_sync(0xFFFFFFFFu, mx0, 1));
        mx0 = fmaxf(mx0, __shfl_xor_sync(0xFFFFFFFFu, mx0, 2));
        mx1 = fmaxf(mx1, __shfl_xor_sync(0xFFFFFFFFu, mx1, 1));
        mx1 = fmaxf(mx1, __shfl_xor_sync(0xFFFFFFFFu, mx1, 2));
        if ((lane & 3) == 0) {
            pmax[r0 * 2 + wn]       = mx0;
            pmax[(r0 + 8) * 2 + wn] = mx1;
        }
        __syncthreads();

        if (tid < 64) {
            float nm = fmaxf(m_s[tid], fmaxf(pmax[tid * 2], pmax[tid * 2 + 1]));
            corr_s[tid] = expf(m_s[tid] - nm);
            m_s[tid] = nm;
        }
        __syncthreads();

        // ---- exp, row sums, P -> bf16 hi/lo smem ----
        float nm0 = m_s[r0], nm1 = m_s[r0 + 8];
        float sum0 = 0.f, sum1 = 0.f;
#pragma unroll
        for (int nt = 0; nt < 4; nt++) {
            int c = wn * 32 + nt * 8 + qc2;
            float p00 = expf(sacc[nt][0] - nm0);
            float p01 = expf(sacc[nt][1] - nm0);
            float p10 = expf(sacc[nt][2] - nm1);
            float p11 = expf(sacc[nt][3] - nm1);
            sum0 += p00 + p01;
            sum1 += p10 + p11;
            __nv_bfloat16 h00 = __float2bfloat16(p00), h01 = __float2bfloat16(p01);
            __nv_bfloat16 h10 = __float2bfloat16(p10), h11 = __float2bfloat16(p11);
            uint32_t hi0 = __bfloat16_as_ushort(h00) | (__bfloat16_as_ushort(h01) << 16);
            uint32_t hi1 = __bfloat16_as_ushort(h10) | (__bfloat16_as_ushort(h11) << 16);
            uint32_t lo0 = __bfloat16_as_ushort(__float2bfloat16(p00 - __bfloat162float(h00)))
                         | (__bfloat16_as_ushort(__float2bfloat16(p01 - __bfloat162float(h01))) << 16);
            uint32_t lo1 = __bfloat16_as_ushort(__float2bfloat16(p10 - __bfloat162float(h10)))
                         | (__bfloat16_as_ushort(__float2bfloat16(p11 - __bfloat162float(h11))) << 16);
            *(uint32_t*)(bsm + OFF_PH + r0 * FPPAD + c)       = hi0;
            *(uint32_t*)(bsm + OFF_PH + (r0 + 8) * FPPAD + c) = hi1;
            *(uint32_t*)(bsm + OFF_PL + r0 * FPPAD + c)       = lo0;
            *(uint32_t*)(bsm + OFF_PL + (r0 + 8) * FPPAD + c) = lo1;
        }
        sum0 += __shfl_xor_sync(0xFFFFFFFFu, sum0, 1);
        sum0 += __shfl_xor_sync(0xFFFFFFFFu, sum0, 2);
        sum1 += __shfl_xor_sync(0xFFFFFFFFu, sum1, 1);
        sum1 += __shfl_xor_sync(0xFFFFFFFFu, sum1, 2);
        if ((lane & 3) == 0) {
            psum[r0 * 2 + wn]       = sum0;
            psum[(r0 + 8) * 2 + wn] = sum1;
        }
        __syncthreads();

        if (tid < 64)
            l_s[tid] = l_s[tid] * corr_s[tid] + psum[tid * 2] + psum[tid * 2 + 1];

        // ---- rescale O by corr ----
        float c0 = corr_s[r0], c1 = corr_s[r0 + 8];
#pragma unroll
        for (int nt = 0; nt < 8; nt++) {
            oacc[nt][0] *= c0; oacc[nt][1] *= c0;
            oacc[nt][2] *= c1; oacc[nt][3] *= c1;
        }

        // ---- O += P V (3-term split), warp tile 16 x 64 ----
#pragma unroll
        for (int jc = 0; jc < 4; jc++) {
            uint32_t pah[4], pal[4], vh[4][4], vl[4][4];
            uint32_t po = sb + (uint32_t)((wm * 16 + lrow) * FPPAD + jc * 16 + lkof) * 2;
            ldm_x4(pah, po + OFF_PH * 2);
            ldm_x4(pal, po + OFF_PL * 2);
#pragma unroll
            for (int nb = 0; nb < 4; nb++) {
                uint32_t vo = sb + (uint32_t)((jc * 16 + lrow) * FQPAD
                                              + wn * 64 + nb * 16 + lkof) * 2;
                ldm_x4_t(vh[nb], vo + OFF_VH * 2);
                ldm_x4_t(vl[nb], vo + OFF_VL * 2);
            }
#pragma unroll
            for (int nb = 0; nb < 4; nb++) {
                mma_bf16(oacc[2*nb],     pah, vh[nb][0], vh[nb][1]);
                mma_bf16(oacc[2*nb],     pah, vl[nb][0], vl[nb][1]);
                mma_bf16(oacc[2*nb],     pal, vh[nb][0], vh[nb][1]);
                mma_bf16(oacc[2*nb + 1], pah, vh[nb][2], vh[nb][3]);
                mma_bf16(oacc[2*nb + 1], pah, vl[nb][2], vl[nb][3]);
                mma_bf16(oacc[2*nb + 1], pal, vh[nb][2], vh[nb][3]);
            }
        }
    }

    // ---- final normalize + write ----
    __syncthreads();
    int r0 = wm * 16 + qr;
    float il0 = 1.0f / l_s[r0], il1 = 1.0f / l_s[r0 + 8];
    size_t ob0 = ((size_t)(b * S_ + qt * 64 + r0)) * H_ + h * HD_;
    size_t ob1 = ob0 + (size_t)8 * H_;
#pragma unroll
    for (int nt = 0; nt < 8; nt++) {
        int col = wn * 64 + nt * 8 + qc2;
        *(float2*)(g_attn + ob0 + col) = make_float2(oacc[nt][0] * il0, oacc[nt][1] * il0);
        *(float2*)(g_attn + ob1 + col) = make_float2(oacc[nt][2] * il1, oacc[nt][3] * il1);
    }
}

// ---------------------------------------------------------------------------
// Launch
// ---------------------------------------------------------------------------
extern "C" void kernel_launch(void* const* d_in, const int* in_sizes, int n_in,
                              void* d_out, int out_size) {
    (void)in_sizes; (void)n_in; (void)out_size;
    const int*   positions = (const int*)d_in[0];
    const float* hidden    = (const float*)d_in[1];
    const float* w_qkv     = (const float*)d_in[2];
    const float* w_out     = (const float*)d_in[3];
    float* out = (float*)d_out;

    float *qkv_p, *attn_p;
    __nv_bfloat16 *hid_h, *hid_l, *wqkv_h, *wqkv_l, *wout_h, *wout_l, *at_h, *at_l;
    cudaGetSymbolAddress((void**)&qkv_p,  g_qkv);
    cudaGetSymbolAddress((void**)&attn_p, g_attn);
    cudaGetSymbolAddress((void**)&hid_h,  g_hid_hi);
    cudaGetSymbolAddress((void**)&hid_l,  g_hid_lo);
    cudaGetSymbolAddress((void**)&wqkv_h, g_wqkvT_hi);
    cudaGetSymbolAddress((void**)&wqkv_l, g_wqkvT_lo);
    cudaGetSymbolAddress((void**)&wout_h, g_woutT_hi);
    cudaGetSymbolAddress((void**)&wout_l, g_woutT_lo);
    cudaGetSymbolAddress((void**)&at_h,   g_attn_hi);
    cudaGetSymbolAddress((void**)&at_l,   g_attn_lo);

    cudaFuncSetAttribute(flash_mma_kernel,
                         cudaFuncAttributeMaxDynamicSharedMemorySize,
                         FLASH_SMEM);
    cudaFuncSetAttribute(mma_gemm_kernel,
                         cudaFuncAttributeMaxDynamicSharedMemorySize,
                         GEMM_SMEM);

    // 0. inv_freq table
    init_invfreq_kernel<<<1, 64>>>();

    // 1. bf16 hi/lo conversions
    split_kernel<<<(M_ * H_ / 4 + 255) / 256, 256>>>(hidden, hid_h, hid_l, M_ * H_ / 4);
    tsplit_kernel<<<dim3(N_QKV / 32, H_ / 32), dim3(32, 8)>>>(w_qkv, wqkv_h, wqkv_l, H_, N_QKV);
    tsplit_kernel<<<dim3(H_ / 32, H_ / 32), dim3(32, 8)>>>(w_out, wout_h, wout_l, H_, H_);

    // 2. QKV projection (HMMA): [4096,4096] x [4096,12288]
    mma_gemm_kernel<<<dim3(M_ / 128, N_QKV / 128), 256, GEMM_SMEM>>>(
        hid_h, hid_l, wqkv_h, wqkv_l, qkv_p, N_QKV, H_);

    // 3. RoPE
    rope_kernel<<<(M_ * NH_ * 64) / 256, 256>>>(positions);

    // 4. Causal flash attention (HMMA, bf16 split)
    flash_mma_kernel<<<dim3(S_ / 64, NH_, B_), 256, FLASH_SMEM>>>();

    // 5. Split attention output, then output projection (HMMA)
    split_kernel<<<(M_ * H_ / 4 + 255) / 256, 256>>>(attn_p, at_h, at_l, M_ * H_ / 4);
    mma_gemm_kernel<<<dim3(M_ / 128, H_ / 128), 256, GEMM_SMEM>>>(
        at_h, at_l, wout_h, wout_l, out, H_, H_);
}